// round 1
// baseline (speedup 1.0000x reference)
#include <cuda_runtime.h>
#include <math.h>

#define NEMAX 200000
#define NCMAX 100000
#define NH 3
#define TILE 64
#define NT 256
#define FCHUNK 64
#define EDIM 200
#define RDIM 128
#define FEA (EDIM + RDIM)   // 328

// ---------------- scratch (device globals; no allocation allowed) -------
__device__ float    g_gate[NH * NEMAX];
__device__ unsigned g_segmax[NH * NCMAX];
__device__ float    g_segsum[NH * NCMAX];

// ---------------- shared memory layout ----------------------------------
struct Smem {
    float bufA[FEA * TILE];     // 328*64 floats = 84 KB
    float bufB[256 * TILE];     // 64 KB
    float Ws[FCHUNK * 256];     // 64 KB weight staging
    int   idx_s[TILE];
};

enum { MODE_FC = 0, MODE_FC_RESID = 1, MODE_ADD = 2 };

// monotone float<->uint key for atomicMax on floats
__device__ __forceinline__ unsigned fkey(float f) {
    unsigned u = __float_as_uint(f);
    return (u & 0x80000000u) ? ~u : (u | 0x80000000u);
}
__device__ __forceinline__ float funkey(unsigned u) {
    return (u & 0x80000000u) ? __uint_as_float(u & 0x7FFFFFFFu)
                             : __uint_as_float(~u);
}

// One dense layer over a 64-elem tile.
// bufIn: [F][64] feature-major, bufOut: [O][64].
// Each active thread computes an 8x8 (elem x out) register micro-tile.
template<int MODE>
__device__ __forceinline__ void layer(const float* __restrict__ Wg,
                                      const float* __restrict__ bg,
                                      int F, int O,
                                      const float* bufIn, float* bufOut,
                                      float* Ws)
{
    const int tid = threadIdx.x;
    const int opt = O >> 3;               // o-tiles of 8
    const int te  = tid / opt;            // elem tile index
    const int to  = tid - te * opt;       // out tile index
    const bool active = (te < 8);

    float acc[8][8];
#pragma unroll
    for (int i = 0; i < 8; i++)
#pragma unroll
        for (int j = 0; j < 8; j++) acc[i][j] = 0.f;

    for (int f0 = 0; f0 < F; f0 += FCHUNK) {
        const int rows = min(FCHUNK, F - f0);
        __syncthreads();   // prev compute done / prev layer writes visible
        {
            const float4* src = reinterpret_cast<const float4*>(Wg + (size_t)f0 * O);
            float4* dst = reinterpret_cast<float4*>(Ws);
            const int tot4 = (rows * O) >> 2;
            for (int i = tid; i < tot4; i += NT) dst[i] = src[i];
        }
        __syncthreads();
        if (active) {
            const float* aB = bufIn + f0 * TILE + te * 8;
            const float* wB = Ws + to * 8;
            for (int f = 0; f < rows; ++f) {
                float a[8], w[8];
#pragma unroll
                for (int i = 0; i < 8; i++) a[i] = aB[f * TILE + i];
#pragma unroll
                for (int j = 0; j < 8; j++) w[j] = wB[f * O + j];
#pragma unroll
                for (int i = 0; i < 8; i++)
#pragma unroll
                    for (int j = 0; j < 8; j++)
                        acc[i][j] = fmaf(a[i], w[j], acc[i][j]);
            }
        }
    }

    if (active) {
        float b[8];
        if (MODE != MODE_ADD) {
#pragma unroll
            for (int j = 0; j < 8; j++) b[j] = bg[to * 8 + j];
        }
#pragma unroll
        for (int j = 0; j < 8; j++) {
            const int o = to * 8 + j;
#pragma unroll
            for (int i = 0; i < 8; i++) {
                const int e = te * 8 + i;
                float v = acc[i][j];
                if (MODE == MODE_FC) {
                    v = fmaxf(v + b[j], 0.f);
                } else if (MODE == MODE_FC_RESID) {
                    v = fmaxf(v + b[j], 0.f) + bufIn[o * TILE + e];
                } else { // MODE_ADD: accumulate residual projection
                    v += bufOut[o * TILE + e];
                }
                bufOut[o * TILE + e] = v;
            }
        }
    }
}

struct P {
    const float* elem; const int* ridx; const float* remb;
    const float *fcW0, *fcb0, *fcW1, *fcb1, *fcW2, *fcb2, *fcW3, *fcb3;
    const float *fcW4, *fcb4, *fcW5, *fcb5, *fcW6, *fcb6;
    const float *resW0, *resW4, *resW6, *outW, *outb;
    int n, c;
};

__global__ void __launch_bounds__(NT, 1) mlp_kernel(P p)
{
    extern __shared__ char smraw[];
    Smem* sm = reinterpret_cast<Smem*>(smraw);
    const int h   = blockIdx.y;
    const int n0  = blockIdx.x * TILE;
    const int tid = threadIdx.x;

    if (tid < TILE)
        sm->idx_s[tid] = (n0 + tid < p.n) ? p.ridx[n0 + tid] : 0;
    __syncthreads();

    // build fea = [orig_elem_fea | reaction_embed[idx]] feature-major into bufA
    for (int i = tid; i < TILE * FEA; i += NT) {
        const int e = i / FEA;
        const int f = i - e * FEA;
        float v = 0.f;
        if (n0 + e < p.n) {
            v = (f < EDIM) ? p.elem[(size_t)(n0 + e) * EDIM + f]
                           : p.remb[(size_t)sm->idx_s[e] * RDIM + (f - EDIM)];
        }
        sm->bufA[f * TILE + e] = v;
    }
    // (layer() begins with __syncthreads, covering the hazard above)

    layer<MODE_FC>      (p.fcW0  + (size_t)h * FEA * 256, p.fcb0 + h * 256, FEA, 256, sm->bufA, sm->bufB, sm->Ws);
    layer<MODE_ADD>     (p.resW0 + (size_t)h * FEA * 256, nullptr,          FEA, 256, sm->bufA, sm->bufB, sm->Ws);
    layer<MODE_FC_RESID>(p.fcW1  + (size_t)h * 256 * 256, p.fcb1 + h * 256, 256, 256, sm->bufB, sm->bufA, sm->Ws);
    layer<MODE_FC_RESID>(p.fcW2  + (size_t)h * 256 * 256, p.fcb2 + h * 256, 256, 256, sm->bufA, sm->bufB, sm->Ws);
    layer<MODE_FC_RESID>(p.fcW3  + (size_t)h * 256 * 256, p.fcb3 + h * 256, 256, 256, sm->bufB, sm->bufA, sm->Ws);
    layer<MODE_FC>      (p.fcW4  + (size_t)h * 256 * 128, p.fcb4 + h * 128, 256, 128, sm->bufA, sm->bufB, sm->Ws);
    layer<MODE_ADD>     (p.resW4 + (size_t)h * 256 * 128, nullptr,          256, 128, sm->bufA, sm->bufB, sm->Ws);
    layer<MODE_FC_RESID>(p.fcW5  + (size_t)h * 128 * 128, p.fcb5 + h * 128, 128, 128, sm->bufB, sm->bufA, sm->Ws);
    layer<MODE_FC>      (p.fcW6  + (size_t)h * 128 * 64,  p.fcb6 + h * 64,  128,  64, sm->bufA, sm->bufB, sm->Ws);
    layer<MODE_ADD>     (p.resW6 + (size_t)h * 128 * 64,  nullptr,          128,  64, sm->bufA, sm->bufB, sm->Ws);
    __syncthreads();

    // final h vector (64 feats) lives in bufB; compute gate per elem
    if (tid < TILE && n0 + tid < p.n) {
        const int e = tid;
        float accv = 0.f;
        const float* ow = p.outW + h * 64;
#pragma unroll
        for (int f = 0; f < 64; ++f)
            accv = fmaf(sm->bufB[f * TILE + e], ow[f], accv);
        const float gate = accv + p.outb[h];
        const int gi = h * p.n + (n0 + e);
        g_gate[gi] = gate;
        atomicMax(&g_segmax[h * p.c + sm->idx_s[e]], fkey(gate));
    }
}

__global__ void init_seg(int total)
{
    const int i = blockIdx.x * blockDim.x + threadIdx.x;
    if (i < total) { g_segmax[i] = 0u; g_segsum[i] = 0.f; }
}

__global__ void exp_kernel(const int* __restrict__ ridx, int n, int c)
{
    const int i = blockIdx.x * blockDim.x + threadIdx.x;
    if (i >= NH * n) return;
    const int hh = i / n;
    const int nn = i - hh * n;
    const int r  = ridx[nn];
    const float m = funkey(g_segmax[hh * c + r]);
    const float e = expf(g_gate[i] - m);
    g_gate[i] = e;
    atomicAdd(&g_segsum[hh * c + r], e);
}

__global__ void out_kernel(const int* __restrict__ ridx,
                           float* __restrict__ out, int n, int c)
{
    const int nn = blockIdx.x * blockDim.x + threadIdx.x;
    if (nn >= n) return;
    const int r = ridx[nn];
    float s = 0.f;
#pragma unroll
    for (int hh = 0; hh < NH; ++hh)
        s += g_gate[hh * n + nn] / (g_segsum[hh * c + r] + 1e-13f);
    out[nn] = s * (1.0f / 3.0f);
}

extern "C" void kernel_launch(void* const* d_in, const int* in_sizes, int n_in,
                              void* d_out, int out_size)
{
    P p;
    p.elem  = (const float*)d_in[0];
    p.ridx  = (const int*)  d_in[1];
    p.remb  = (const float*)d_in[2];
    p.fcW0  = (const float*)d_in[3];  p.fcb0 = (const float*)d_in[4];
    p.fcW1  = (const float*)d_in[5];  p.fcb1 = (const float*)d_in[6];
    p.fcW2  = (const float*)d_in[7];  p.fcb2 = (const float*)d_in[8];
    p.fcW3  = (const float*)d_in[9];  p.fcb3 = (const float*)d_in[10];
    p.fcW4  = (const float*)d_in[11]; p.fcb4 = (const float*)d_in[12];
    p.fcW5  = (const float*)d_in[13]; p.fcb5 = (const float*)d_in[14];
    p.fcW6  = (const float*)d_in[15]; p.fcb6 = (const float*)d_in[16];
    p.resW0 = (const float*)d_in[17];
    p.resW4 = (const float*)d_in[18];
    p.resW6 = (const float*)d_in[19];
    p.outW  = (const float*)d_in[20];
    p.outb  = (const float*)d_in[21];
    p.n = in_sizes[1];            // N elems
    p.c = in_sizes[2] / RDIM;     // N reactions

    static bool smem_set = false;
    if (!smem_set) {
        cudaFuncSetAttribute(mlp_kernel,
                             cudaFuncAttributeMaxDynamicSharedMemorySize,
                             (int)sizeof(Smem));
        smem_set = true;
    }

    const int segs = NH * p.c;
    init_seg<<<(segs + 255) / 256, 256>>>(segs);

    dim3 grid((p.n + TILE - 1) / TILE, NH);
    mlp_kernel<<<grid, NT, sizeof(Smem)>>>(p);

    const int tot = NH * p.n;
    exp_kernel<<<(tot + 255) / 256, 256>>>(p.ridx, p.n, p.c);
    out_kernel<<<(p.n + 255) / 256, 256>>>(p.ridx, (float*)d_out, p.n, p.c);
}

// round 2
// speedup vs baseline: 1.0263x; 1.0263x over previous
#include <cuda_runtime.h>
#include <math.h>

#define NEMAX 200000
#define NCMAX 100000
#define NH 3
#define TILE 64
#define NT 256
#define FCHUNK 64
#define EDIM 200
#define RDIM 128
#define FEA (EDIM + RDIM)   // 328

typedef unsigned long long u64;

// ---------------- scratch (device globals; no allocation allowed) -------
__device__ float    g_gate[NH * NEMAX];
__device__ unsigned g_segmax[NH * NCMAX];
__device__ float    g_segsum[NH * NCMAX];

// ---------------- shared memory layout ----------------------------------
struct Smem {
    float bufA[FEA * TILE];     // 328*64 floats = 84 KB
    float bufB[256 * TILE];     // 64 KB
    float Ws[FCHUNK * 256];     // 64 KB weight staging
    int   idx_s[TILE];
};

enum { MODE_FC = 0, MODE_FC_RESID = 1, MODE_ADD = 2 };

// monotone float<->uint key for atomicMax on floats
__device__ __forceinline__ unsigned fkey(float f) {
    unsigned u = __float_as_uint(f);
    return (u & 0x80000000u) ? ~u : (u | 0x80000000u);
}
__device__ __forceinline__ float funkey(unsigned u) {
    return (u & 0x80000000u) ? __uint_as_float(u & 0x7FFFFFFFu)
                             : __uint_as_float(~u);
}

// Blackwell packed fp32 pair FMA (SASS FFMA2) — only reachable via PTX.
__device__ __forceinline__ void fma2(u64& d, u64 a, u64 b) {
    asm volatile("fma.rn.f32x2 %0, %1, %2, %0;" : "+l"(d) : "l"(a), "l"(b));
}
__device__ __forceinline__ u64 dup2(float x) {
    u64 r;
    unsigned xb = __float_as_uint(x);
    asm("mov.b64 %0, {%1, %1};" : "=l"(r) : "r"(xb));
    return r;
}
__device__ __forceinline__ void unpack2(u64 v, float& lo, float& hi) {
    unsigned a, b;
    asm("mov.b64 {%0, %1}, %2;" : "=r"(a), "=r"(b) : "l"(v));
    lo = __uint_as_float(a);
    hi = __uint_as_float(b);
}

// One dense layer over a 64-elem tile.
// bufIn: [F][64] feature-major, bufOut: [O][64].
// Each active thread computes an 8x8 (elem x out) register micro-tile,
// accumulated as 8x4 packed fp32 pairs along the out dim (FFMA2).
template<int MODE>
__device__ __forceinline__ void layer(const float* __restrict__ Wg,
                                      const float* __restrict__ bg,
                                      int F, int O,
                                      const float* bufIn, float* bufOut,
                                      float* Ws)
{
    const int tid = threadIdx.x;
    const int opt = O >> 3;               // o-tiles of 8
    const int te  = tid / opt;            // elem tile index
    const int to  = tid - te * opt;       // out tile index
    const bool active = (te < 8);

    u64 acc[8][4];
#pragma unroll
    for (int i = 0; i < 8; i++)
#pragma unroll
        for (int j = 0; j < 4; j++) acc[i][j] = 0ull;

    for (int f0 = 0; f0 < F; f0 += FCHUNK) {
        const int rows = min(FCHUNK, F - f0);
        __syncthreads();   // prev compute done / prev layer writes visible
        {
            const float4* src = reinterpret_cast<const float4*>(Wg + (size_t)f0 * O);
            float4* dst = reinterpret_cast<float4*>(Ws);
            const int tot4 = (rows * O) >> 2;
            for (int i = tid; i < tot4; i += NT) dst[i] = src[i];
        }
        __syncthreads();
        if (active) {
            const float* aB = bufIn + f0 * TILE + te * 8;
            const float* wB = Ws + to * 8;
#pragma unroll 2
            for (int f = 0; f < rows; ++f) {
                // a: 8 consecutive elem activations (warp-broadcast)
                float4 a0 = *reinterpret_cast<const float4*>(aB + f * TILE);
                float4 a1 = *reinterpret_cast<const float4*>(aB + f * TILE + 4);
                u64 ad[8];
                ad[0] = dup2(a0.x); ad[1] = dup2(a0.y);
                ad[2] = dup2(a0.z); ad[3] = dup2(a0.w);
                ad[4] = dup2(a1.x); ad[5] = dup2(a1.y);
                ad[6] = dup2(a1.z); ad[7] = dup2(a1.w);
                // w: 4 packed pairs (8 consecutive outs)
                ulonglong2 w01 = *reinterpret_cast<const ulonglong2*>(wB + f * O);
                ulonglong2 w23 = *reinterpret_cast<const ulonglong2*>(wB + f * O + 4);
                u64 wp[4] = { w01.x, w01.y, w23.x, w23.y };
#pragma unroll
                for (int i = 0; i < 8; i++)
#pragma unroll
                    for (int j = 0; j < 4; j++)
                        fma2(acc[i][j], ad[i], wp[j]);
            }
        }
    }

    if (active) {
        float b[8];
        if (MODE != MODE_ADD) {
#pragma unroll
            for (int j = 0; j < 8; j++) b[j] = bg[to * 8 + j];
        }
#pragma unroll
        for (int j2 = 0; j2 < 4; j2++) {
#pragma unroll
            for (int i = 0; i < 8; i++) {
                const int e = te * 8 + i;
                float vlo, vhi;
                unpack2(acc[i][j2], vlo, vhi);
                const int olo = to * 8 + j2 * 2;
                const int ohi = olo + 1;
                if (MODE == MODE_FC) {
                    vlo = fmaxf(vlo + b[j2 * 2], 0.f);
                    vhi = fmaxf(vhi + b[j2 * 2 + 1], 0.f);
                } else if (MODE == MODE_FC_RESID) {
                    vlo = fmaxf(vlo + b[j2 * 2], 0.f)     + bufIn[olo * TILE + e];
                    vhi = fmaxf(vhi + b[j2 * 2 + 1], 0.f) + bufIn[ohi * TILE + e];
                } else { // MODE_ADD: accumulate residual projection
                    vlo += bufOut[olo * TILE + e];
                    vhi += bufOut[ohi * TILE + e];
                }
                bufOut[olo * TILE + e] = vlo;
                bufOut[ohi * TILE + e] = vhi;
            }
        }
    }
}

struct P {
    const float* elem; const int* ridx; const float* remb;
    const float *fcW0, *fcb0, *fcW1, *fcb1, *fcW2, *fcb2, *fcW3, *fcb3;
    const float *fcW4, *fcb4, *fcW5, *fcb5, *fcW6, *fcb6;
    const float *resW0, *resW4, *resW6, *outW, *outb;
    int n, c;
};

__global__ void __launch_bounds__(NT, 1) mlp_kernel(P p)
{
    extern __shared__ char smraw[];
    Smem* sm = reinterpret_cast<Smem*>(smraw);
    const int h   = blockIdx.y;
    const int n0  = blockIdx.x * TILE;
    const int tid = threadIdx.x;

    if (tid < TILE)
        sm->idx_s[tid] = (n0 + tid < p.n) ? p.ridx[n0 + tid] : 0;
    __syncthreads();

    // build fea = [orig_elem_fea | reaction_embed[idx]] feature-major into bufA
    for (int i = tid; i < TILE * FEA; i += NT) {
        const int e = i / FEA;
        const int f = i - e * FEA;
        float v = 0.f;
        if (n0 + e < p.n) {
            v = (f < EDIM) ? p.elem[(size_t)(n0 + e) * EDIM + f]
                           : p.remb[(size_t)sm->idx_s[e] * RDIM + (f - EDIM)];
        }
        sm->bufA[f * TILE + e] = v;
    }
    // (layer() begins with __syncthreads, covering the hazard above)

    layer<MODE_FC>      (p.fcW0  + (size_t)h * FEA * 256, p.fcb0 + h * 256, FEA, 256, sm->bufA, sm->bufB, sm->Ws);
    layer<MODE_ADD>     (p.resW0 + (size_t)h * FEA * 256, nullptr,          FEA, 256, sm->bufA, sm->bufB, sm->Ws);
    layer<MODE_FC_RESID>(p.fcW1  + (size_t)h * 256 * 256, p.fcb1 + h * 256, 256, 256, sm->bufB, sm->bufA, sm->Ws);
    layer<MODE_FC_RESID>(p.fcW2  + (size_t)h * 256 * 256, p.fcb2 + h * 256, 256, 256, sm->bufA, sm->bufB, sm->Ws);
    layer<MODE_FC_RESID>(p.fcW3  + (size_t)h * 256 * 256, p.fcb3 + h * 256, 256, 256, sm->bufB, sm->bufA, sm->Ws);
    layer<MODE_FC>      (p.fcW4  + (size_t)h * 256 * 128, p.fcb4 + h * 128, 256, 128, sm->bufA, sm->bufB, sm->Ws);
    layer<MODE_ADD>     (p.resW4 + (size_t)h * 256 * 128, nullptr,          256, 128, sm->bufA, sm->bufB, sm->Ws);
    layer<MODE_FC_RESID>(p.fcW5  + (size_t)h * 128 * 128, p.fcb5 + h * 128, 128, 128, sm->bufB, sm->bufA, sm->Ws);
    layer<MODE_FC>      (p.fcW6  + (size_t)h * 128 * 64,  p.fcb6 + h * 64,  128,  64, sm->bufA, sm->bufB, sm->Ws);
    layer<MODE_ADD>     (p.resW6 + (size_t)h * 128 * 64,  nullptr,          128,  64, sm->bufA, sm->bufB, sm->Ws);
    __syncthreads();

    // final h vector (64 feats) lives in bufB; compute gate per elem
    if (tid < TILE && n0 + tid < p.n) {
        const int e = tid;
        float accv = 0.f;
        const float* ow = p.outW + h * 64;
#pragma unroll
        for (int f = 0; f < 64; ++f)
            accv = fmaf(sm->bufB[f * TILE + e], ow[f], accv);
        const float gate = accv + p.outb[h];
        const int gi = h * p.n + (n0 + e);
        g_gate[gi] = gate;
        atomicMax(&g_segmax[h * p.c + sm->idx_s[e]], fkey(gate));
    }
}

__global__ void init_seg(int total)
{
    const int i = blockIdx.x * blockDim.x + threadIdx.x;
    if (i < total) { g_segmax[i] = 0u; g_segsum[i] = 0.f; }
}

__global__ void exp_kernel(const int* __restrict__ ridx, int n, int c)
{
    const int i = blockIdx.x * blockDim.x + threadIdx.x;
    if (i >= NH * n) return;
    const int hh = i / n;
    const int nn = i - hh * n;
    const int r  = ridx[nn];
    const float m = funkey(g_segmax[hh * c + r]);
    const float e = expf(g_gate[i] - m);
    g_gate[i] = e;
    atomicAdd(&g_segsum[hh * c + r], e);
}

__global__ void out_kernel(const int* __restrict__ ridx,
                           float* __restrict__ out, int n, int c)
{
    const int nn = blockIdx.x * blockDim.x + threadIdx.x;
    if (nn >= n) return;
    const int r = ridx[nn];
    float s = 0.f;
#pragma unroll
    for (int hh = 0; hh < NH; ++hh)
        s += g_gate[hh * n + nn] / (g_segsum[hh * c + r] + 1e-13f);
    out[nn] = s * (1.0f / 3.0f);
}

extern "C" void kernel_launch(void* const* d_in, const int* in_sizes, int n_in,
                              void* d_out, int out_size)
{
    P p;
    p.elem  = (const float*)d_in[0];
    p.ridx  = (const int*)  d_in[1];
    p.remb  = (const float*)d_in[2];
    p.fcW0  = (const float*)d_in[3];  p.fcb0 = (const float*)d_in[4];
    p.fcW1  = (const float*)d_in[5];  p.fcb1 = (const float*)d_in[6];
    p.fcW2  = (const float*)d_in[7];  p.fcb2 = (const float*)d_in[8];
    p.fcW3  = (const float*)d_in[9];  p.fcb3 = (const float*)d_in[10];
    p.fcW4  = (const float*)d_in[11]; p.fcb4 = (const float*)d_in[12];
    p.fcW5  = (const float*)d_in[13]; p.fcb5 = (const float*)d_in[14];
    p.fcW6  = (const float*)d_in[15]; p.fcb6 = (const float*)d_in[16];
    p.resW0 = (const float*)d_in[17];
    p.resW4 = (const float*)d_in[18];
    p.resW6 = (const float*)d_in[19];
    p.outW  = (const float*)d_in[20];
    p.outb  = (const float*)d_in[21];
    p.n = in_sizes[1];            // N elems
    p.c = in_sizes[2] / RDIM;     // N reactions

    static bool smem_set = false;
    if (!smem_set) {
        cudaFuncSetAttribute(mlp_kernel,
                             cudaFuncAttributeMaxDynamicSharedMemorySize,
                             (int)sizeof(Smem));
        smem_set = true;
    }

    const int segs = NH * p.c;
    init_seg<<<(segs + 255) / 256, 256>>>(segs);

    dim3 grid((p.n + TILE - 1) / TILE, NH);
    mlp_kernel<<<grid, NT, sizeof(Smem)>>>(p);

    const int tot = NH * p.n;
    exp_kernel<<<(tot + 255) / 256, 256>>>(p.ridx, p.n, p.c);
    out_kernel<<<(p.n + 255) / 256, 256>>>(p.ridx, (float*)d_out, p.n, p.c);
}